// round 2
// baseline (speedup 1.0000x reference)
#include <cuda_runtime.h>

// Problem constants
#define N_ENT    100000
#define N_REL    250000
#define N_TRIG   50000
#define N_ARGS   250000
#define ENT_DIM  288
#define REL_R    256
#define RTYPE_DIM 32
#define ROLE_DIM 256
#define ARG_DIM  576
#define KDIM     1152   // 2 * ARG_DIM : [S_in | S_out] per trigger
#define OUT_DIM  544    // ENT_DIM + ROLE_DIM

// Scratch: per-trigger masked feature sums. 50000 * 1152 * 4B = 230.4 MB
__device__ float g_S[(size_t)N_TRIG * KDIM];

// ---------------------------------------------------------------------------
// Zero the accumulator
// ---------------------------------------------------------------------------
__global__ void __launch_bounds__(256) zero_S() {
    const size_t n4 = (size_t)N_TRIG * KDIM / 4;
    float4* p = reinterpret_cast<float4*>(g_S);
    const float4 z = make_float4(0.f, 0.f, 0.f, 0.f);
    for (size_t i = (size_t)blockIdx.x * blockDim.x + threadIdx.x; i < n4;
         i += (size_t)gridDim.x * blockDim.x)
        p[i] = z;
}

// ---------------------------------------------------------------------------
// Scatter: one warp per argument. Gathers [rel | rtype | ent] (576 floats)
// and atomically adds into S[trig, base:base+576] where base = is_in ? 0 : 576.
// ---------------------------------------------------------------------------
__device__ __forceinline__ void red4(float* p, float4 v) {
    asm volatile("red.global.add.v4.f32 [%0], {%1,%2,%3,%4};"
                 :: "l"(p), "f"(v.x), "f"(v.y), "f"(v.z), "f"(v.w)
                 : "memory");
}

__global__ void __launch_bounds__(256) scatter_args(
    const float* __restrict__ ent, const float* __restrict__ rel,
    const float* __restrict__ rtt, const int* __restrict__ rtype_ids,
    const int* __restrict__ arg_trig, const int* __restrict__ arg_rel,
    const int* __restrict__ arg_ent, const int* __restrict__ arg_is_in)
{
    const int w    = (blockIdx.x * 256 + threadIdx.x) >> 5;
    const int lane = threadIdx.x & 31;
    if (w >= N_ARGS) return;

    const int t  = __ldg(arg_trig + w);
    const int r  = __ldg(arg_rel + w);
    const int e  = __ldg(arg_ent + w);
    const int in = __ldg(arg_is_in + w);

    float* dst = g_S + (size_t)t * KDIM + (in ? 0 : ARG_DIM);

    const float4* relp = reinterpret_cast<const float4*>(rel + (size_t)r * REL_R);
    const float4* entp = reinterpret_cast<const float4*>(ent + (size_t)e * ENT_DIM);
    const float4* rtp  = reinterpret_cast<const float4*>(
        rtt + (size_t)__ldg(rtype_ids + r) * RTYPE_DIM);

    // rel part: 256 floats = 64 float4 -> dst[0:256)
    red4(dst + (size_t)lane * 4,        relp[lane]);
    red4(dst + (size_t)(lane + 32) * 4, relp[lane + 32]);
    // rtype part: 32 floats = 8 float4 -> dst[256:288)
    if (lane < 8)
        red4(dst + 256 + (size_t)lane * 4, rtp[lane]);
    // ent part: 288 floats = 72 float4 -> dst[288:576)
    red4(dst + 288 + (size_t)lane * 4,        entp[lane]);
    red4(dst + 288 + (size_t)(lane + 32) * 4, entp[lane + 32]);
    if (lane < 8)
        red4(dst + 288 + (size_t)(lane + 64) * 4, entp[lane + 64]);
}

// ---------------------------------------------------------------------------
// Copy trigger entity embedding into out[:, 0:288]. One warp per trigger.
// ---------------------------------------------------------------------------
__global__ void __launch_bounds__(256) copy_trig(
    const float* __restrict__ ent, const int* __restrict__ trig_ent_id,
    float* __restrict__ out)
{
    const int w    = (blockIdx.x * 256 + threadIdx.x) >> 5;
    const int lane = threadIdx.x & 31;
    if (w >= N_TRIG) return;
    const float4* src = reinterpret_cast<const float4*>(
        ent + (size_t)__ldg(trig_ent_id + w) * ENT_DIM);
    float4* dst = reinterpret_cast<float4*>(out + (size_t)w * OUT_DIM);
    dst[lane]      = src[lane];
    dst[lane + 32] = src[lane + 32];
    if (lane < 8) dst[lane + 64] = src[lane + 64];
}

// ---------------------------------------------------------------------------
// SGEMM: C[50000,256] = S[50000,1152] @ Wcat[1152,256]
//   Wcat rows [0:576)   = W_in
//   Wcat rows [576:1152) = W_out
// Epilogue writes out[m, 288 + n]. 128x128x16 tiles, 256 threads, 8x8 micro,
// double-buffered smem.
// ---------------------------------------------------------------------------
#define BM 128
#define BN 128
#define BK 16
#define TM 8
#define TN 8

__global__ void __launch_bounds__(256, 2) gemm_out(
    const float* __restrict__ W_in, const float* __restrict__ W_out,
    float* __restrict__ out)
{
    __shared__ __align__(16) float As[2][BK][BM + 4];
    __shared__ __align__(16) float Bs[2][BK][BN];

    const int tid = threadIdx.x;
    const int m0 = blockIdx.y * BM;
    const int n0 = blockIdx.x * BN;

    const int tx = tid & 15;     // 0..15 -> 8 cols each
    const int ty = tid >> 4;     // 0..15 -> 8 rows each

    // global-load thread mapping
    const int arow  = tid >> 2;  // 0..63  (A rows, two passes: +0, +64)
    const int acol4 = tid & 3;   // 0..3   (float4 within BK=16)
    const int brow  = tid >> 5;  // 0..7   (B k-rows, two passes: +0, +8)
    const int bcol4 = tid & 31;  // 0..31  (float4 within BN=128)

    const float* A = g_S;

    float acc[TM][TN];
    #pragma unroll
    for (int i = 0; i < TM; i++)
        #pragma unroll
        for (int j = 0; j < TN; j++) acc[i][j] = 0.f;

    float4 aSt[2], bSt[2];

    auto loadA = [&](int k0) {
        #pragma unroll
        for (int s = 0; s < 2; s++) {
            int m = m0 + arow + s * 64;
            if (m < N_TRIG)
                aSt[s] = *reinterpret_cast<const float4*>(
                    A + (size_t)m * KDIM + k0 + acol4 * 4);
            else
                aSt[s] = make_float4(0.f, 0.f, 0.f, 0.f);
        }
    };
    auto loadB = [&](int k0) {
        #pragma unroll
        for (int s = 0; s < 2; s++) {
            int k = k0 + brow + s * 8;
            const float* Wp = (k < ARG_DIM)
                ? (W_in + (size_t)k * ROLE_DIM)
                : (W_out + (size_t)(k - ARG_DIM) * ROLE_DIM);
            bSt[s] = *reinterpret_cast<const float4*>(Wp + n0 + bcol4 * 4);
        }
    };
    auto storeAB = [&](int buf) {
        #pragma unroll
        for (int s = 0; s < 2; s++) {
            int m = arow + s * 64;
            As[buf][acol4 * 4 + 0][m] = aSt[s].x;
            As[buf][acol4 * 4 + 1][m] = aSt[s].y;
            As[buf][acol4 * 4 + 2][m] = aSt[s].z;
            As[buf][acol4 * 4 + 3][m] = aSt[s].w;
        }
        #pragma unroll
        for (int s = 0; s < 2; s++)
            *reinterpret_cast<float4*>(&Bs[buf][brow + s * 8][bcol4 * 4]) = bSt[s];
    };

    loadA(0); loadB(0);
    storeAB(0);
    __syncthreads();

    const int nk = KDIM / BK;  // 72
    int buf = 0;
    for (int kt = 0; kt < nk; kt++) {
        if (kt + 1 < nk) { loadA((kt + 1) * BK); loadB((kt + 1) * BK); }

        #pragma unroll
        for (int k = 0; k < BK; k++) {
            float af[TM], bf[TN];
            #pragma unroll
            for (int i = 0; i < TM; i += 4)
                *reinterpret_cast<float4*>(&af[i]) =
                    *reinterpret_cast<const float4*>(&As[buf][k][ty * TM + i]);
            #pragma unroll
            for (int j = 0; j < TN; j += 4)
                *reinterpret_cast<float4*>(&bf[j]) =
                    *reinterpret_cast<const float4*>(&Bs[buf][k][tx * TN + j]);
            #pragma unroll
            for (int i = 0; i < TM; i++)
                #pragma unroll
                for (int j = 0; j < TN; j++)
                    acc[i][j] += af[i] * bf[j];
        }

        if (kt + 1 < nk) storeAB(buf ^ 1);
        __syncthreads();
        buf ^= 1;
    }

    // Epilogue: out[m, 288 + n]
    #pragma unroll
    for (int i = 0; i < TM; i++) {
        int m = m0 + ty * TM + i;
        if (m < N_TRIG) {
            float* op = out + (size_t)m * OUT_DIM + ENT_DIM + n0 + tx * TN;
            *reinterpret_cast<float4*>(op) =
                make_float4(acc[i][0], acc[i][1], acc[i][2], acc[i][3]);
            *reinterpret_cast<float4*>(op + 4) =
                make_float4(acc[i][4], acc[i][5], acc[i][6], acc[i][7]);
        }
    }
}

// ---------------------------------------------------------------------------
extern "C" void kernel_launch(void* const* d_in, const int* in_sizes, int n_in,
                              void* d_out, int out_size)
{
    const float* ent        = (const float*)d_in[0];
    const float* rel        = (const float*)d_in[1];
    const float* rtt        = (const float*)d_in[2];
    const float* W_in       = (const float*)d_in[3];
    const float* W_out      = (const float*)d_in[4];
    const int*   rtype_ids  = (const int*)d_in[5];
    const int*   trig_ent   = (const int*)d_in[6];
    const int*   arg_trig   = (const int*)d_in[7];
    const int*   arg_rel    = (const int*)d_in[8];
    const int*   arg_ent    = (const int*)d_in[9];
    const int*   arg_is_in  = (const int*)d_in[10];
    float* out = (float*)d_out;

    (void)in_sizes; (void)n_in; (void)out_size;

    zero_S<<<2048, 256>>>();
    scatter_args<<<(N_ARGS * 32 + 255) / 256, 256>>>(
        ent, rel, rtt, rtype_ids, arg_trig, arg_rel, arg_ent, arg_is_in);
    copy_trig<<<(N_TRIG * 32 + 255) / 256, 256>>>(ent, trig_ent, out);

    dim3 grid(ROLE_DIM / BN, (N_TRIG + BM - 1) / BM);  // (2, 391)
    gemm_out<<<grid, 256>>>(W_in, W_out, out);
}

// round 5
// speedup vs baseline: 2.0819x; 2.0819x over previous
#include <cuda_runtime.h>
#include <cstdint>

#define N_ENT    100000
#define N_REL    250000
#define N_TRIG   50000
#define N_ARGS   250000
#define ENT_DIM  288
#define REL_R    256
#define RTYPE_DIM 32
#define ROLE_DIM 256
#define ARG_DIM  576
#define KDIM     1152
#define OUT_DIM  544

// Scratch
__device__ float g_S[(size_t)N_TRIG * KDIM];     // 230.4 MB per-trigger masked sums
__device__ float g_Wt[(size_t)ROLE_DIM * KDIM];  // 1.18 MB: Wcat^T [256,1152], tf32-rounded

// ---------------------------------------------------------------------------
// helpers
// ---------------------------------------------------------------------------
__device__ __forceinline__ uint32_t f2tf32(float f) {
    uint32_t r;
    asm("cvt.rna.tf32.f32 %0, %1;" : "=r"(r) : "f"(f));
    return r;
}
__device__ __forceinline__ void mma_tf32(float* c, const uint32_t* a, const uint32_t* b) {
    asm volatile(
        "mma.sync.aligned.m16n8k8.row.col.f32.tf32.tf32.f32 "
        "{%0,%1,%2,%3}, {%4,%5,%6,%7}, {%8,%9}, {%0,%1,%2,%3};"
        : "+f"(c[0]), "+f"(c[1]), "+f"(c[2]), "+f"(c[3])
        : "r"(a[0]), "r"(a[1]), "r"(a[2]), "r"(a[3]), "r"(b[0]), "r"(b[1]));
}
__device__ __forceinline__ void cpa16(uint32_t s, const void* g) {
    asm volatile("cp.async.cg.shared.global [%0], [%1], 16;" :: "r"(s), "l"(g));
}
__device__ __forceinline__ uint32_t smem_u32(const void* p) {
    uint32_t a;
    asm("{ .reg .u64 t; cvta.to.shared.u64 t, %1; cvt.u32.u64 %0, t; }"
        : "=r"(a) : "l"(p));
    return a;
}

// ---------------------------------------------------------------------------
// Zero the accumulator
// ---------------------------------------------------------------------------
__global__ void __launch_bounds__(256) zero_S() {
    const size_t n4 = (size_t)N_TRIG * KDIM / 4;
    float4* p = reinterpret_cast<float4*>(g_S);
    const float4 z = make_float4(0.f, 0.f, 0.f, 0.f);
    for (size_t i = (size_t)blockIdx.x * blockDim.x + threadIdx.x; i < n4;
         i += (size_t)gridDim.x * blockDim.x)
        p[i] = z;
}

// ---------------------------------------------------------------------------
// Scatter: one warp per argument -> atomic add into g_S
// ---------------------------------------------------------------------------
__device__ __forceinline__ void red4(float* p, float4 v) {
    asm volatile("red.global.add.v4.f32 [%0], {%1,%2,%3,%4};"
                 :: "l"(p), "f"(v.x), "f"(v.y), "f"(v.z), "f"(v.w) : "memory");
}

__global__ void __launch_bounds__(256) scatter_args(
    const float* __restrict__ ent, const float* __restrict__ rel,
    const float* __restrict__ rtt, const int* __restrict__ rtype_ids,
    const int* __restrict__ arg_trig, const int* __restrict__ arg_rel,
    const int* __restrict__ arg_ent, const int* __restrict__ arg_is_in)
{
    const int w    = (blockIdx.x * 256 + threadIdx.x) >> 5;
    const int lane = threadIdx.x & 31;
    if (w >= N_ARGS) return;

    const int t  = __ldg(arg_trig + w);
    const int r  = __ldg(arg_rel + w);
    const int e  = __ldg(arg_ent + w);
    const int in = __ldg(arg_is_in + w);

    float* dst = g_S + (size_t)t * KDIM + (in ? 0 : ARG_DIM);

    const float4* relp = reinterpret_cast<const float4*>(rel + (size_t)r * REL_R);
    const float4* entp = reinterpret_cast<const float4*>(ent + (size_t)e * ENT_DIM);
    const float4* rtp  = reinterpret_cast<const float4*>(
        rtt + (size_t)__ldg(rtype_ids + r) * RTYPE_DIM);

    red4(dst + (size_t)lane * 4,        relp[lane]);
    red4(dst + (size_t)(lane + 32) * 4, relp[lane + 32]);
    if (lane < 8) red4(dst + 256 + (size_t)lane * 4, rtp[lane]);
    red4(dst + 288 + (size_t)lane * 4,        entp[lane]);
    red4(dst + 288 + (size_t)(lane + 32) * 4, entp[lane + 32]);
    if (lane < 8) red4(dst + 288 + (size_t)(lane + 64) * 4, entp[lane + 64]);
}

// ---------------------------------------------------------------------------
// Trigger entity embedding -> out[:, 0:288]
// ---------------------------------------------------------------------------
__global__ void __launch_bounds__(256) copy_trig(
    const float* __restrict__ ent, const int* __restrict__ trig_ent_id,
    float* __restrict__ out)
{
    const int w    = (blockIdx.x * 256 + threadIdx.x) >> 5;
    const int lane = threadIdx.x & 31;
    if (w >= N_TRIG) return;
    const float4* src = reinterpret_cast<const float4*>(
        ent + (size_t)__ldg(trig_ent_id + w) * ENT_DIM);
    float4* dst = reinterpret_cast<float4*>(out + (size_t)w * OUT_DIM);
    dst[lane]      = src[lane];
    dst[lane + 32] = src[lane + 32];
    if (lane < 8) dst[lane + 64] = src[lane + 64];
}

// ---------------------------------------------------------------------------
// Wt[n][k] = tf32_round( k < 576 ? W_in[k][n] : W_out[k-576][n] )
// ---------------------------------------------------------------------------
__global__ void __launch_bounds__(128) transpose_W(
    const float* __restrict__ W_in, const float* __restrict__ W_out)
{
    const int n = blockIdx.x;  // 0..255
    for (int k = threadIdx.x; k < KDIM; k += 128) {
        float w = (k < ARG_DIM) ? __ldg(W_in  + (size_t)k * ROLE_DIM + n)
                                : __ldg(W_out + (size_t)(k - ARG_DIM) * ROLE_DIM + n);
        g_Wt[(size_t)n * KDIM + k] = __uint_as_float(f2tf32(w));
    }
}

// ---------------------------------------------------------------------------
// tf32 mma.sync GEMM: C[50000,256] = g_S[50000,1152] @ g_Wt^T
// BM=128, BN=256 (full N), BK=32, 8 warps (4M x 2N), warp tile 32x128.
// cp.async double-buffered. Epilogue -> out[m, 288+n].
// ---------------------------------------------------------------------------
#define BM 128
#define BK 32
#define LDA 40          // BK + 4 pad (floats); row stride 160B (16B-mult)
#define NKCH (KDIM / BK)  // 36

#define A_BUF_FL (BM * LDA)          // 5120 floats = 20480 B
#define B_BUF_FL (ROLE_DIM * LDA)    // 10240 floats = 40960 B
#define SM_TOTAL ((2 * A_BUF_FL + 2 * B_BUF_FL) * 4)  // 122880 B

__global__ void __launch_bounds__(256, 1) gemm_tc(float* __restrict__ out)
{
    extern __shared__ __align__(1024) float smem[];
    float* As = smem;                    // [2][BM][LDA]
    float* Bs = smem + 2 * A_BUF_FL;     // [2][256][LDA]
    const uint32_t sbA = smem_u32(As);
    const uint32_t sbB = smem_u32(Bs);

    const int tid  = threadIdx.x;
    const int wid  = tid >> 5;
    const int lane = tid & 31;
    const int wm   = wid & 3;     // 0..3 -> M offset wm*32
    const int wn   = wid >> 2;    // 0..1 -> N offset wn*128
    const int qr   = lane >> 2;   // 0..7
    const int qc   = lane & 3;    // 0..3
    const int m0   = blockIdx.x * BM;

    float acc[2][16][4];
    #pragma unroll
    for (int mi = 0; mi < 2; mi++)
        #pragma unroll
        for (int ni = 0; ni < 16; ni++)
            #pragma unroll
            for (int q = 0; q < 4; q++) acc[mi][ni][q] = 0.f;

    auto load_chunk = [&](int c, int buf) {
        const int k0 = c * BK;
        const uint32_t aB = sbA + buf * (A_BUF_FL * 4);
        const uint32_t bB = sbB + buf * (B_BUF_FL * 4);
        // A: 128 rows x 8 segs of 16B
        #pragma unroll
        for (int j = 0; j < 4; j++) {
            const int idx = tid + j * 256;
            const int row = idx >> 3, seg = idx & 7;
            int m = m0 + row; if (m > N_TRIG - 1) m = N_TRIG - 1;
            cpa16(aB + (uint32_t)(row * LDA + seg * 4) * 4,
                  g_S + (size_t)m * KDIM + k0 + seg * 4);
        }
        // B: 256 rows x 8 segs of 16B
        #pragma unroll
        for (int j = 0; j < 8; j++) {
            const int idx = tid + j * 256;
            const int row = idx >> 3, seg = idx & 7;
            cpa16(bB + (uint32_t)(row * LDA + seg * 4) * 4,
                  g_Wt + (size_t)row * KDIM + k0 + seg * 4);
        }
        asm volatile("cp.async.commit_group;" ::: "memory");
    };

    load_chunk(0, 0);
    load_chunk(1, 1);

    for (int c = 0; c < NKCH; c++) {
        const int buf = c & 1;
        if (c + 2 < NKCH) asm volatile("cp.async.wait_group 1;" ::: "memory");
        else              asm volatile("cp.async.wait_group 0;" ::: "memory");
        __syncthreads();

        const float* A = As + buf * A_BUF_FL;
        const float* B = Bs + buf * B_BUF_FL;

        #pragma unroll
        for (int ks = 0; ks < 4; ks++) {
            const int kk = ks * 8;
            uint32_t a[2][4];
            #pragma unroll
            for (int mi = 0; mi < 2; mi++) {
                const int r = wm * 32 + mi * 16 + qr;
                a[mi][0] = f2tf32(A[r * LDA + kk + qc]);
                a[mi][1] = f2tf32(A[(r + 8) * LDA + kk + qc]);
                a[mi][2] = f2tf32(A[r * LDA + kk + qc + 4]);
                a[mi][3] = f2tf32(A[(r + 8) * LDA + kk + qc + 4]);
            }
            #pragma unroll
            for (int h = 0; h < 2; h++) {          // two groups of 8 N-tiles
                uint32_t b[8][2];
                #pragma unroll
                for (int nj = 0; nj < 8; nj++) {
                    const int cb = wn * 128 + (h * 8 + nj) * 8 + qr;
                    b[nj][0] = __float_as_uint(B[cb * LDA + kk + qc]);
                    b[nj][1] = __float_as_uint(B[cb * LDA + kk + qc + 4]);
                }
                #pragma unroll
                for (int mi = 0; mi < 2; mi++)
                    #pragma unroll
                    for (int nj = 0; nj < 8; nj++)
                        mma_tf32(acc[mi][h * 8 + nj], a[mi], b[nj]);
            }
        }
        __syncthreads();
        if (c + 2 < NKCH) load_chunk(c + 2, buf);
    }

    // Epilogue: out[m, 288 + n]
    #pragma unroll
    for (int mi = 0; mi < 2; mi++) {
        const int m_lo = m0 + wm * 32 + mi * 16 + qr;
        #pragma unroll
        for (int ni = 0; ni < 16; ni++) {
            const int n = ENT_DIM + wn * 128 + ni * 8 + qc * 2;
            if (m_lo < N_TRIG)
                *reinterpret_cast<float2*>(out + (size_t)m_lo * OUT_DIM + n) =
                    make_float2(acc[mi][ni][0], acc[mi][ni][1]);
            if (m_lo + 8 < N_TRIG)
                *reinterpret_cast<float2*>(out + (size_t)(m_lo + 8) * OUT_DIM + n) =
                    make_float2(acc[mi][ni][2], acc[mi][ni][3]);
        }
    }
}

// ---------------------------------------------------------------------------
extern "C" void kernel_launch(void* const* d_in, const int* in_sizes, int n_in,
                              void* d_out, int out_size)
{
    const float* ent       = (const float*)d_in[0];
    const float* rel       = (const float*)d_in[1];
    const float* rtt       = (const float*)d_in[2];
    const float* W_in      = (const float*)d_in[3];
    const float* W_out     = (const float*)d_in[4];
    const int*   rtype_ids = (const int*)d_in[5];
    const int*   trig_ent  = (const int*)d_in[6];
    const int*   arg_trig  = (const int*)d_in[7];
    const int*   arg_rel   = (const int*)d_in[8];
    const int*   arg_ent   = (const int*)d_in[9];
    const int*   arg_is_in = (const int*)d_in[10];
    float* out = (float*)d_out;

    (void)in_sizes; (void)n_in; (void)out_size;

    transpose_W<<<ROLE_DIM, 128>>>(W_in, W_out);
    zero_S<<<2048, 256>>>();
    scatter_args<<<(N_ARGS * 32 + 255) / 256, 256>>>(
        ent, rel, rtt, rtype_ids, arg_trig, arg_rel, arg_ent, arg_is_in);
    copy_trig<<<(N_TRIG * 32 + 255) / 256, 256>>>(ent, trig_ent, out);

    cudaFuncSetAttribute(gemm_tc, cudaFuncAttributeMaxDynamicSharedMemorySize, SM_TOTAL);
    gemm_tc<<<(N_TRIG + BM - 1) / BM, 256, SM_TOTAL>>>(out);
}

// round 6
// speedup vs baseline: 2.1935x; 1.0536x over previous
#include <cuda_runtime.h>
#include <cstdint>

#define N_ENT    100000
#define N_REL    250000
#define N_TRIG   50000
#define N_ARGS   250000
#define ENT_DIM  288
#define REL_R    256
#define RTYPE_DIM 32
#define ROLE_DIM 256
#define ARG_DIM  576
#define KDIM     1152
#define OUT_DIM  544

#define NKEY     (N_TRIG * 2)     // 100000 (trig, side) segments
#define NKEY_PAD 102400           // multiple of 4096 for the scan kernel

// Scratch
__device__ float g_S[(size_t)N_TRIG * KDIM];     // 230.4 MB per-trigger masked sums
__device__ float g_Wt[(size_t)ROLE_DIM * KDIM];  // 1.18 MB: Wcat^T [256,1152], tf32-rounded
__device__ int   g_cnt[NKEY_PAD];                // per-key arg counts
__device__ int   g_off[NKEY + 1];                // CSR offsets
__device__ int   g_cur[NKEY];                    // fill cursors
__device__ int4  g_rec[N_ARGS];                  // {rel, ent, rtype, 0} sorted by key

// ---------------------------------------------------------------------------
// helpers
// ---------------------------------------------------------------------------
__device__ __forceinline__ uint32_t f2tf32(float f) {
    uint32_t r;
    asm("cvt.rna.tf32.f32 %0, %1;" : "=r"(r) : "f"(f));
    return r;
}
__device__ __forceinline__ void mma_tf32(float* c, const uint32_t* a, const uint32_t* b) {
    asm volatile(
        "mma.sync.aligned.m16n8k8.row.col.f32.tf32.tf32.f32 "
        "{%0,%1,%2,%3}, {%4,%5,%6,%7}, {%8,%9}, {%0,%1,%2,%3};"
        : "+f"(c[0]), "+f"(c[1]), "+f"(c[2]), "+f"(c[3])
        : "r"(a[0]), "r"(a[1]), "r"(a[2]), "r"(a[3]), "r"(b[0]), "r"(b[1]));
}
__device__ __forceinline__ void cpa16(uint32_t s, const void* g) {
    asm volatile("cp.async.cg.shared.global [%0], [%1], 16;" :: "r"(s), "l"(g));
}
__device__ __forceinline__ uint32_t smem_u32(const void* p) {
    uint32_t a;
    asm("{ .reg .u64 t; cvta.to.shared.u64 t, %1; cvt.u32.u64 %0, t; }"
        : "=r"(a) : "l"(p));
    return a;
}

// ---------------------------------------------------------------------------
// Wt[n][k] = tf32_round( k < 576 ? W_in[k][n] : W_out[k-576][n] )
// ---------------------------------------------------------------------------
__global__ void __launch_bounds__(128) transpose_W(
    const float* __restrict__ W_in, const float* __restrict__ W_out)
{
    const int n = blockIdx.x;  // 0..255
    for (int k = threadIdx.x; k < KDIM; k += 128) {
        float w = (k < ARG_DIM) ? __ldg(W_in  + (size_t)k * ROLE_DIM + n)
                                : __ldg(W_out + (size_t)(k - ARG_DIM) * ROLE_DIM + n);
        g_Wt[(size_t)n * KDIM + k] = __uint_as_float(f2tf32(w));
    }
}

// ---------------------------------------------------------------------------
// CSR build: zero counts -> histogram -> scan -> fill records
// ---------------------------------------------------------------------------
__global__ void __launch_bounds__(256) zero_cnt() {
    int i = blockIdx.x * 256 + threadIdx.x;
    if (i < NKEY_PAD) g_cnt[i] = 0;
}

__global__ void __launch_bounds__(256) hist_args(
    const int* __restrict__ arg_trig, const int* __restrict__ arg_is_in)
{
    int i = blockIdx.x * 256 + threadIdx.x;
    if (i >= N_ARGS) return;
    atomicAdd(&g_cnt[arg_trig[i] * 2 + arg_is_in[i]], 1);
}

// single-block exclusive scan over NKEY counts, 4 elems/thread per pass
__global__ void __launch_bounds__(1024) scan_keys()
{
    __shared__ int s[1024];
    const int tid = threadIdx.x;
    int total = 0;
    for (int base = 0; base < NKEY_PAD; base += 4096) {
        int4 v = *reinterpret_cast<const int4*>(g_cnt + base + tid * 4);
        int sum4 = v.x + v.y + v.z + v.w;
        s[tid] = sum4;
        __syncthreads();
        #pragma unroll
        for (int d = 1; d < 1024; d <<= 1) {
            int add = (tid >= d) ? s[tid - d] : 0;
            __syncthreads();
            s[tid] += add;
            __syncthreads();
        }
        int excl = total + s[tid] - sum4;      // exclusive prefix for this thread's 4
        int bsum = s[1023];
        __syncthreads();
        int i0 = base + tid * 4;
        int o0 = excl;
        int o1 = o0 + v.x;
        int o2 = o1 + v.y;
        int o3 = o2 + v.z;
        if (i0 + 0 < NKEY) { g_off[i0 + 0] = o0; g_cur[i0 + 0] = o0; }
        if (i0 + 1 < NKEY) { g_off[i0 + 1] = o1; g_cur[i0 + 1] = o1; }
        if (i0 + 2 < NKEY) { g_off[i0 + 2] = o2; g_cur[i0 + 2] = o2; }
        if (i0 + 3 < NKEY) { g_off[i0 + 3] = o3; g_cur[i0 + 3] = o3; }
        total += bsum;
    }
    if (tid == 0) g_off[NKEY] = total;
}

__global__ void __launch_bounds__(256) fill_args(
    const int* __restrict__ arg_trig, const int* __restrict__ arg_rel,
    const int* __restrict__ arg_ent, const int* __restrict__ arg_is_in,
    const int* __restrict__ rtype_ids)
{
    int i = blockIdx.x * 256 + threadIdx.x;
    if (i >= N_ARGS) return;
    const int key = arg_trig[i] * 2 + arg_is_in[i];
    const int r   = arg_rel[i];
    const int pos = atomicAdd(&g_cur[key], 1);
    g_rec[pos] = make_int4(r, arg_ent[i], __ldg(rtype_ids + r), 0);
}

// ---------------------------------------------------------------------------
// Aggregate: one warp per (trigger, side). Sums arg feature rows in registers,
// writes the 576-float half-row of g_S once (zeros if no args). No atomics.
// key = t*2 + is_in ; is_in==1 -> S[t, 0:576], is_in==0 -> S[t, 576:1152]
// ---------------------------------------------------------------------------
__global__ void __launch_bounds__(256) aggregate(
    const float* __restrict__ ent, const float* __restrict__ rel,
    const float* __restrict__ rtt)
{
    const int w    = (blockIdx.x * 256 + threadIdx.x) >> 5;
    const int lane = threadIdx.x & 31;
    if (w >= NKEY) return;

    const int t    = w >> 1;
    const int isin = w & 1;
    const int off  = __ldg(g_off + w);
    const int end  = __ldg(g_off + w + 1);

    float acc[18];
    #pragma unroll
    for (int j = 0; j < 18; j++) acc[j] = 0.f;

    for (int p = off; p < end; p++) {
        const int4 rec = __ldg(g_rec + p);
        const float* relp = rel + (size_t)rec.x * REL_R;
        const float* entp = ent + (size_t)rec.y * ENT_DIM;
        const float* rtp  = rtt + (size_t)rec.z * RTYPE_DIM;
        float v[18];
        #pragma unroll
        for (int j = 0; j < 8; j++)  v[j] = __ldg(relp + j * 32 + lane);
        v[8] = __ldg(rtp + lane);
        #pragma unroll
        for (int j = 9; j < 18; j++) v[j] = __ldg(entp + (j - 9) * 32 + lane);
        #pragma unroll
        for (int j = 0; j < 18; j++) acc[j] += v[j];
    }

    float* dst = g_S + (size_t)t * KDIM + (isin ? 0 : ARG_DIM);
    #pragma unroll
    for (int j = 0; j < 18; j++) dst[j * 32 + lane] = acc[j];
}

// ---------------------------------------------------------------------------
// Trigger entity embedding -> out[:, 0:288]
// ---------------------------------------------------------------------------
__global__ void __launch_bounds__(256) copy_trig(
    const float* __restrict__ ent, const int* __restrict__ trig_ent_id,
    float* __restrict__ out)
{
    const int w    = (blockIdx.x * 256 + threadIdx.x) >> 5;
    const int lane = threadIdx.x & 31;
    if (w >= N_TRIG) return;
    const float4* src = reinterpret_cast<const float4*>(
        ent + (size_t)__ldg(trig_ent_id + w) * ENT_DIM);
    float4* dst = reinterpret_cast<float4*>(out + (size_t)w * OUT_DIM);
    dst[lane]      = src[lane];
    dst[lane + 32] = src[lane + 32];
    if (lane < 8) dst[lane + 64] = src[lane + 64];
}

// ---------------------------------------------------------------------------
// tf32 mma.sync GEMM: C[50000,256] = g_S[50000,1152] @ g_Wt^T
// BM=128, BN=256 (full N), BK=32, 8 warps (4M x 2N), warp tile 32x128.
// ---------------------------------------------------------------------------
#define BM 128
#define BK 32
#define LDA 40
#define NKCH (KDIM / BK)  // 36

#define A_BUF_FL (BM * LDA)
#define B_BUF_FL (ROLE_DIM * LDA)
#define SM_TOTAL ((2 * A_BUF_FL + 2 * B_BUF_FL) * 4)  // 122880 B

__global__ void __launch_bounds__(256, 1) gemm_tc(float* __restrict__ out)
{
    extern __shared__ __align__(1024) float smem[];
    float* As = smem;
    float* Bs = smem + 2 * A_BUF_FL;
    const uint32_t sbA = smem_u32(As);
    const uint32_t sbB = smem_u32(Bs);

    const int tid  = threadIdx.x;
    const int wid  = tid >> 5;
    const int lane = tid & 31;
    const int wm   = wid & 3;
    const int wn   = wid >> 2;
    const int qr   = lane >> 2;
    const int qc   = lane & 3;
    const int m0   = blockIdx.x * BM;

    float acc[2][16][4];
    #pragma unroll
    for (int mi = 0; mi < 2; mi++)
        #pragma unroll
        for (int ni = 0; ni < 16; ni++)
            #pragma unroll
            for (int q = 0; q < 4; q++) acc[mi][ni][q] = 0.f;

    auto load_chunk = [&](int c, int buf) {
        const int k0 = c * BK;
        const uint32_t aB = sbA + buf * (A_BUF_FL * 4);
        const uint32_t bB = sbB + buf * (B_BUF_FL * 4);
        #pragma unroll
        for (int j = 0; j < 4; j++) {
            const int idx = tid + j * 256;
            const int row = idx >> 3, seg = idx & 7;
            int m = m0 + row; if (m > N_TRIG - 1) m = N_TRIG - 1;
            cpa16(aB + (uint32_t)(row * LDA + seg * 4) * 4,
                  g_S + (size_t)m * KDIM + k0 + seg * 4);
        }
        #pragma unroll
        for (int j = 0; j < 8; j++) {
            const int idx = tid + j * 256;
            const int row = idx >> 3, seg = idx & 7;
            cpa16(bB + (uint32_t)(row * LDA + seg * 4) * 4,
                  g_Wt + (size_t)row * KDIM + k0 + seg * 4);
        }
        asm volatile("cp.async.commit_group;" ::: "memory");
    };

    load_chunk(0, 0);
    load_chunk(1, 1);

    for (int c = 0; c < NKCH; c++) {
        const int buf = c & 1;
        if (c + 2 < NKCH) asm volatile("cp.async.wait_group 1;" ::: "memory");
        else              asm volatile("cp.async.wait_group 0;" ::: "memory");
        __syncthreads();

        const float* A = As + buf * A_BUF_FL;
        const float* B = Bs + buf * B_BUF_FL;

        #pragma unroll
        for (int ks = 0; ks < 4; ks++) {
            const int kk = ks * 8;
            uint32_t a[2][4];
            #pragma unroll
            for (int mi = 0; mi < 2; mi++) {
                const int r = wm * 32 + mi * 16 + qr;
                a[mi][0] = f2tf32(A[r * LDA + kk + qc]);
                a[mi][1] = f2tf32(A[(r + 8) * LDA + kk + qc]);
                a[mi][2] = f2tf32(A[r * LDA + kk + qc + 4]);
                a[mi][3] = f2tf32(A[(r + 8) * LDA + kk + qc + 4]);
            }
            #pragma unroll
            for (int h = 0; h < 2; h++) {
                uint32_t b[8][2];
                #pragma unroll
                for (int nj = 0; nj < 8; nj++) {
                    const int cb = wn * 128 + (h * 8 + nj) * 8 + qr;
                    b[nj][0] = __float_as_uint(B[cb * LDA + kk + qc]);
                    b[nj][1] = __float_as_uint(B[cb * LDA + kk + qc + 4]);
                }
                #pragma unroll
                for (int mi = 0; mi < 2; mi++)
                    #pragma unroll
                    for (int nj = 0; nj < 8; nj++)
                        mma_tf32(acc[mi][h * 8 + nj], a[mi], b[nj]);
            }
        }
        __syncthreads();
        if (c + 2 < NKCH) load_chunk(c + 2, buf);
    }

    #pragma unroll
    for (int mi = 0; mi < 2; mi++) {
        const int m_lo = m0 + wm * 32 + mi * 16 + qr;
        #pragma unroll
        for (int ni = 0; ni < 16; ni++) {
            const int n = ENT_DIM + wn * 128 + ni * 8 + qc * 2;
            if (m_lo < N_TRIG)
                *reinterpret_cast<float2*>(out + (size_t)m_lo * OUT_DIM + n) =
                    make_float2(acc[mi][ni][0], acc[mi][ni][1]);
            if (m_lo + 8 < N_TRIG)
                *reinterpret_cast<float2*>(out + (size_t)(m_lo + 8) * OUT_DIM + n) =
                    make_float2(acc[mi][ni][2], acc[mi][ni][3]);
        }
    }
}

// ---------------------------------------------------------------------------
extern "C" void kernel_launch(void* const* d_in, const int* in_sizes, int n_in,
                              void* d_out, int out_size)
{
    const float* ent       = (const float*)d_in[0];
    const float* rel       = (const float*)d_in[1];
    const float* rtt       = (const float*)d_in[2];
    const float* W_in      = (const float*)d_in[3];
    const float* W_out     = (const float*)d_in[4];
    const int*   rtype_ids = (const int*)d_in[5];
    const int*   trig_ent  = (const int*)d_in[6];
    const int*   arg_trig  = (const int*)d_in[7];
    const int*   arg_rel   = (const int*)d_in[8];
    const int*   arg_ent   = (const int*)d_in[9];
    const int*   arg_is_in = (const int*)d_in[10];
    float* out = (float*)d_out;

    (void)in_sizes; (void)n_in; (void)out_size;

    transpose_W<<<ROLE_DIM, 128>>>(W_in, W_out);                      // launch 0
    zero_cnt<<<(NKEY_PAD + 255) / 256, 256>>>();                      // launch 1
    hist_args<<<(N_ARGS + 255) / 256, 256>>>(arg_trig, arg_is_in);    // launch 2
    scan_keys<<<1, 1024>>>();                                         // launch 3
    fill_args<<<(N_ARGS + 255) / 256, 256>>>(                         // launch 4
        arg_trig, arg_rel, arg_ent, arg_is_in, rtype_ids);
    aggregate<<<(NKEY * 32 + 255) / 256, 256>>>(ent, rel, rtt);       // launch 5
    copy_trig<<<(N_TRIG * 32 + 255) / 256, 256>>>(ent, trig_ent, out);// launch 6

    cudaFuncSetAttribute(gemm_tc, cudaFuncAttributeMaxDynamicSharedMemorySize, SM_TOTAL);
    gemm_tc<<<(N_TRIG + BM - 1) / BM, 256, SM_TOTAL>>>(out);          // launch 7
}

// round 7
// speedup vs baseline: 2.2103x; 1.0076x over previous
#include <cuda_runtime.h>
#include <cstdint>

#define N_ENT    100000
#define N_REL    250000
#define N_TRIG   50000
#define N_ARGS   250000
#define ENT_DIM  288
#define REL_R    256
#define RTYPE_DIM 32
#define ROLE_DIM 256
#define ARG_DIM  576
#define KDIM     1152
#define OUT_DIM  544

#define NKEY     (N_TRIG * 2)     // 100000 (trig, side) segments
#define NKEY_PAD 102400           // 25 * 4096
#define NSCAN_IT (NKEY_PAD / 4096)

// Scratch
__device__ float g_S[(size_t)N_TRIG * KDIM];     // 230.4 MB per-trigger masked sums
__device__ float g_Wt[(size_t)ROLE_DIM * KDIM];  // 1.18 MB: Wcat^T [256,1152], tf32-rounded
__device__ int   g_cnt[NKEY_PAD];                // per-key arg counts
__device__ int   g_off[NKEY + 1];                // CSR offsets
__device__ int   g_cur[NKEY];                    // fill cursors
__device__ int4  g_rec[N_ARGS];                  // {rel, ent, rtype, 0} sorted by key

// ---------------------------------------------------------------------------
// helpers
// ---------------------------------------------------------------------------
__device__ __forceinline__ uint32_t f2tf32(float f) {
    uint32_t r;
    asm("cvt.rna.tf32.f32 %0, %1;" : "=r"(r) : "f"(f));
    return r;
}
__device__ __forceinline__ void mma_tf32(float* c, const uint32_t* a, const uint32_t* b) {
    asm volatile(
        "mma.sync.aligned.m16n8k8.row.col.f32.tf32.tf32.f32 "
        "{%0,%1,%2,%3}, {%4,%5,%6,%7}, {%8,%9}, {%0,%1,%2,%3};"
        : "+f"(c[0]), "+f"(c[1]), "+f"(c[2]), "+f"(c[3])
        : "r"(a[0]), "r"(a[1]), "r"(a[2]), "r"(a[3]), "r"(b[0]), "r"(b[1]));
}
__device__ __forceinline__ void cpa16(uint32_t s, const void* g) {
    asm volatile("cp.async.cg.shared.global [%0], [%1], 16;" :: "r"(s), "l"(g));
}
__device__ __forceinline__ uint32_t smem_u32(const void* p) {
    uint32_t a;
    asm("{ .reg .u64 t; cvta.to.shared.u64 t, %1; cvt.u32.u64 %0, t; }"
        : "=r"(a) : "l"(p));
    return a;
}

// ---------------------------------------------------------------------------
// Wt[n][k] = tf32_round( k < 576 ? W_in[k][n] : W_out[k-576][n] )
// ---------------------------------------------------------------------------
__global__ void __launch_bounds__(128) transpose_W(
    const float* __restrict__ W_in, const float* __restrict__ W_out)
{
    const int n = blockIdx.x;  // 0..255
    for (int k = threadIdx.x; k < KDIM; k += 128) {
        float w = (k < ARG_DIM) ? __ldg(W_in  + (size_t)k * ROLE_DIM + n)
                                : __ldg(W_out + (size_t)(k - ARG_DIM) * ROLE_DIM + n);
        g_Wt[(size_t)n * KDIM + k] = __uint_as_float(f2tf32(w));
    }
}

// ---------------------------------------------------------------------------
// CSR build: zero counts -> histogram -> scan -> fill records
// ---------------------------------------------------------------------------
__global__ void __launch_bounds__(256) zero_cnt() {
    int i = blockIdx.x * 256 + threadIdx.x;
    if (i < NKEY_PAD) g_cnt[i] = 0;
}

__global__ void __launch_bounds__(256) hist_args(
    const int* __restrict__ arg_trig, const int* __restrict__ arg_is_in)
{
    int i = blockIdx.x * 256 + threadIdx.x;
    if (i >= N_ARGS) return;
    atomicAdd(&g_cnt[arg_trig[i] * 2 + arg_is_in[i]], 1);
}

// single-block exclusive scan: warp-shuffle scans, 2 barriers/chunk, prefetch
__global__ void __launch_bounds__(1024) scan_keys()
{
    __shared__ int wsum[32];
    __shared__ int blktot;
    const int tid  = threadIdx.x;
    const int lane = tid & 31;
    const int warp = tid >> 5;

    int carry = 0;
    int4 v = *reinterpret_cast<const int4*>(g_cnt + tid * 4);

    for (int it = 0; it < NSCAN_IT; it++) {
        const int base = it * 4096;
        int4 vn;
        if (it + 1 < NSCAN_IT)
            vn = *reinterpret_cast<const int4*>(g_cnt + base + 4096 + tid * 4);

        const int s4 = v.x + v.y + v.z + v.w;
        // warp inclusive scan of s4
        int inc = s4;
        #pragma unroll
        for (int d = 1; d < 32; d <<= 1) {
            int t = __shfl_up_sync(0xFFFFFFFFu, inc, d);
            if (lane >= d) inc += t;
        }
        if (lane == 31) wsum[warp] = inc;
        __syncthreads();
        if (warp == 0) {
            int w = wsum[lane];
            int wi = w;
            #pragma unroll
            for (int d = 1; d < 32; d <<= 1) {
                int t = __shfl_up_sync(0xFFFFFFFFu, wi, d);
                if (lane >= d) wi += t;
            }
            wsum[lane] = wi - w;           // exclusive
            if (lane == 31) blktot = wi;
        }
        __syncthreads();

        const int excl = carry + wsum[warp] + inc - s4;
        const int i0 = base + tid * 4;
        const int o0 = excl;
        const int o1 = o0 + v.x;
        const int o2 = o1 + v.y;
        const int o3 = o2 + v.z;
        if (i0 + 0 < NKEY) { g_off[i0 + 0] = o0; g_cur[i0 + 0] = o0; }
        if (i0 + 1 < NKEY) { g_off[i0 + 1] = o1; g_cur[i0 + 1] = o1; }
        if (i0 + 2 < NKEY) { g_off[i0 + 2] = o2; g_cur[i0 + 2] = o2; }
        if (i0 + 3 < NKEY) { g_off[i0 + 3] = o3; g_cur[i0 + 3] = o3; }
        carry += blktot;
        v = vn;
    }
    if (tid == 0) g_off[NKEY] = carry;
}

__global__ void __launch_bounds__(256) fill_args(
    const int* __restrict__ arg_trig, const int* __restrict__ arg_rel,
    const int* __restrict__ arg_ent, const int* __restrict__ arg_is_in,
    const int* __restrict__ rtype_ids)
{
    int i = blockIdx.x * 256 + threadIdx.x;
    if (i >= N_ARGS) return;
    const int key = arg_trig[i] * 2 + arg_is_in[i];
    const int r   = arg_rel[i];
    const int pos = atomicAdd(&g_cur[key], 1);
    g_rec[pos] = make_int4(r, arg_ent[i], __ldg(rtype_ids + r), 0);
}

// ---------------------------------------------------------------------------
// Aggregate: one warp per (trigger, side). float4 gathers, register acc,
// one coalesced float4 write of the 576-float half-row. No atomics.
// ---------------------------------------------------------------------------
__global__ void __launch_bounds__(256) aggregate(
    const float* __restrict__ ent, const float* __restrict__ rel,
    const float* __restrict__ rtt)
{
    const int w    = (blockIdx.x * 256 + threadIdx.x) >> 5;
    const int lane = threadIdx.x & 31;
    if (w >= NKEY) return;

    const int t    = w >> 1;
    const int isin = w & 1;
    const int off  = __ldg(g_off + w);
    const int end  = __ldg(g_off + w + 1);
    const bool lo8 = lane < 8;

    const float4 z = make_float4(0.f, 0.f, 0.f, 0.f);
    float4 aR0 = z, aR1 = z, aT = z, aE0 = z, aE1 = z, aE2 = z;

    for (int p = off; p < end; p++) {
        const int4 rec = __ldg(g_rec + p);
        const float4* relp = reinterpret_cast<const float4*>(rel + (size_t)rec.x * REL_R);
        const float4* entp = reinterpret_cast<const float4*>(ent + (size_t)rec.y * ENT_DIM);
        const float4* rtp  = reinterpret_cast<const float4*>(rtt + (size_t)rec.z * RTYPE_DIM);

        const float4 r0 = __ldg(relp + lane);
        const float4 r1 = __ldg(relp + lane + 32);
        const float4 e0 = __ldg(entp + lane);
        const float4 e1 = __ldg(entp + lane + 32);
        float4 t0 = z, e2 = z;
        if (lo8) { t0 = __ldg(rtp + lane); e2 = __ldg(entp + lane + 64); }

        aR0.x += r0.x; aR0.y += r0.y; aR0.z += r0.z; aR0.w += r0.w;
        aR1.x += r1.x; aR1.y += r1.y; aR1.z += r1.z; aR1.w += r1.w;
        aT.x  += t0.x; aT.y  += t0.y; aT.z  += t0.z; aT.w  += t0.w;
        aE0.x += e0.x; aE0.y += e0.y; aE0.z += e0.z; aE0.w += e0.w;
        aE1.x += e1.x; aE1.y += e1.y; aE1.z += e1.z; aE1.w += e1.w;
        aE2.x += e2.x; aE2.y += e2.y; aE2.z += e2.z; aE2.w += e2.w;
    }

    float4* d4 = reinterpret_cast<float4*>(
        g_S + (size_t)t * KDIM + (isin ? 0 : ARG_DIM));
    d4[lane]      = aR0;           // rel cols 0..255
    d4[lane + 32] = aR1;
    d4[72 + lane]      = aE0;      // ent cols 288..575
    d4[72 + lane + 32] = aE1;
    if (lo8) {
        d4[64 + lane]  = aT;       // rtype cols 256..287
        d4[136 + lane] = aE2;
    }
}

// ---------------------------------------------------------------------------
// Trigger entity embedding -> out[:, 0:288]
// ---------------------------------------------------------------------------
__global__ void __launch_bounds__(256) copy_trig(
    const float* __restrict__ ent, const int* __restrict__ trig_ent_id,
    float* __restrict__ out)
{
    const int w    = (blockIdx.x * 256 + threadIdx.x) >> 5;
    const int lane = threadIdx.x & 31;
    if (w >= N_TRIG) return;
    const float4* src = reinterpret_cast<const float4*>(
        ent + (size_t)__ldg(trig_ent_id + w) * ENT_DIM);
    float4* dst = reinterpret_cast<float4*>(out + (size_t)w * OUT_DIM);
    dst[lane]      = src[lane];
    dst[lane + 32] = src[lane + 32];
    if (lane < 8) dst[lane + 64] = src[lane + 64];
}

// ---------------------------------------------------------------------------
// tf32 mma.sync GEMM: C[50000,256] = g_S[50000,1152] @ g_Wt^T
// BM=128, BN=256 (full N), BK=32, 8 warps (4M x 2N), warp tile 32x128.
// ---------------------------------------------------------------------------
#define BM 128
#define BK 32
#define LDA 40
#define NKCH (KDIM / BK)  // 36

#define A_BUF_FL (BM * LDA)
#define B_BUF_FL (ROLE_DIM * LDA)
#define SM_TOTAL ((2 * A_BUF_FL + 2 * B_BUF_FL) * 4)  // 122880 B

__global__ void __launch_bounds__(256, 1) gemm_tc(float* __restrict__ out)
{
    extern __shared__ __align__(1024) float smem[];
    float* As = smem;
    float* Bs = smem + 2 * A_BUF_FL;
    const uint32_t sbA = smem_u32(As);
    const uint32_t sbB = smem_u32(Bs);

    const int tid  = threadIdx.x;
    const int wid  = tid >> 5;
    const int lane = tid & 31;
    const int wm   = wid & 3;
    const int wn   = wid >> 2;
    const int qr   = lane >> 2;
    const int qc   = lane & 3;
    const int m0   = blockIdx.x * BM;

    float acc[2][16][4];
    #pragma unroll
    for (int mi = 0; mi < 2; mi++)
        #pragma unroll
        for (int ni = 0; ni < 16; ni++)
            #pragma unroll
            for (int q = 0; q < 4; q++) acc[mi][ni][q] = 0.f;

    auto load_chunk = [&](int c, int buf) {
        const int k0 = c * BK;
        const uint32_t aB = sbA + buf * (A_BUF_FL * 4);
        const uint32_t bB = sbB + buf * (B_BUF_FL * 4);
        #pragma unroll
        for (int j = 0; j < 4; j++) {
            const int idx = tid + j * 256;
            const int row = idx >> 3, seg = idx & 7;
            int m = m0 + row; if (m > N_TRIG - 1) m = N_TRIG - 1;
            cpa16(aB + (uint32_t)(row * LDA + seg * 4) * 4,
                  g_S + (size_t)m * KDIM + k0 + seg * 4);
        }
        #pragma unroll
        for (int j = 0; j < 8; j++) {
            const int idx = tid + j * 256;
            const int row = idx >> 3, seg = idx & 7;
            cpa16(bB + (uint32_t)(row * LDA + seg * 4) * 4,
                  g_Wt + (size_t)row * KDIM + k0 + seg * 4);
        }
        asm volatile("cp.async.commit_group;" ::: "memory");
    };

    load_chunk(0, 0);
    load_chunk(1, 1);

    for (int c = 0; c < NKCH; c++) {
        const int buf = c & 1;
        if (c + 2 < NKCH) asm volatile("cp.async.wait_group 1;" ::: "memory");
        else              asm volatile("cp.async.wait_group 0;" ::: "memory");
        __syncthreads();

        const float* A = As + buf * A_BUF_FL;
        const float* B = Bs + buf * B_BUF_FL;

        #pragma unroll
        for (int ks = 0; ks < 4; ks++) {
            const int kk = ks * 8;
            uint32_t a[2][4];
            #pragma unroll
            for (int mi = 0; mi < 2; mi++) {
                const int r = wm * 32 + mi * 16 + qr;
                a[mi][0] = f2tf32(A[r * LDA + kk + qc]);
                a[mi][1] = f2tf32(A[(r + 8) * LDA + kk + qc]);
                a[mi][2] = f2tf32(A[r * LDA + kk + qc + 4]);
                a[mi][3] = f2tf32(A[(r + 8) * LDA + kk + qc + 4]);
            }
            #pragma unroll
            for (int h = 0; h < 2; h++) {
                uint32_t b[8][2];
                #pragma unroll
                for (int nj = 0; nj < 8; nj++) {
                    const int cb = wn * 128 + (h * 8 + nj) * 8 + qr;
                    b[nj][0] = __float_as_uint(B[cb * LDA + kk + qc]);
                    b[nj][1] = __float_as_uint(B[cb * LDA + kk + qc + 4]);
                }
                #pragma unroll
                for (int mi = 0; mi < 2; mi++)
                    #pragma unroll
                    for (int nj = 0; nj < 8; nj++)
                        mma_tf32(acc[mi][h * 8 + nj], a[mi], b[nj]);
            }
        }
        __syncthreads();
        if (c + 2 < NKCH) load_chunk(c + 2, buf);
    }

    #pragma unroll
    for (int mi = 0; mi < 2; mi++) {
        const int m_lo = m0 + wm * 32 + mi * 16 + qr;
        #pragma unroll
        for (int ni = 0; ni < 16; ni++) {
            const int n = ENT_DIM + wn * 128 + ni * 8 + qc * 2;
            if (m_lo < N_TRIG)
                *reinterpret_cast<float2*>(out + (size_t)m_lo * OUT_DIM + n) =
                    make_float2(acc[mi][ni][0], acc[mi][ni][1]);
            if (m_lo + 8 < N_TRIG)
                *reinterpret_cast<float2*>(out + (size_t)(m_lo + 8) * OUT_DIM + n) =
                    make_float2(acc[mi][ni][2], acc[mi][ni][3]);
        }
    }
}

// ---------------------------------------------------------------------------
extern "C" void kernel_launch(void* const* d_in, const int* in_sizes, int n_in,
                              void* d_out, int out_size)
{
    const float* ent       = (const float*)d_in[0];
    const float* rel       = (const float*)d_in[1];
    const float* rtt       = (const float*)d_in[2];
    const float* W_in      = (const float*)d_in[3];
    const float* W_out     = (const float*)d_in[4];
    const int*   rtype_ids = (const int*)d_in[5];
    const int*   trig_ent  = (const int*)d_in[6];
    const int*   arg_trig  = (const int*)d_in[7];
    const int*   arg_rel   = (const int*)d_in[8];
    const int*   arg_ent   = (const int*)d_in[9];
    const int*   arg_is_in = (const int*)d_in[10];
    float* out = (float*)d_out;

    (void)in_sizes; (void)n_in; (void)out_size;

    transpose_W<<<ROLE_DIM, 128>>>(W_in, W_out);
    zero_cnt<<<(NKEY_PAD + 255) / 256, 256>>>();
    hist_args<<<(N_ARGS + 255) / 256, 256>>>(arg_trig, arg_is_in);
    scan_keys<<<1, 1024>>>();
    fill_args<<<(N_ARGS + 255) / 256, 256>>>(
        arg_trig, arg_rel, arg_ent, arg_is_in, rtype_ids);
    aggregate<<<(NKEY * 32 + 255) / 256, 256>>>(ent, rel, rtt);
    copy_trig<<<(N_TRIG * 32 + 255) / 256, 256>>>(ent, trig_ent, out);

    cudaFuncSetAttribute(gemm_tc, cudaFuncAttributeMaxDynamicSharedMemorySize, SM_TOTAL);
    gemm_tc<<<(N_TRIG + BM - 1) / BM, 256, SM_TOTAL>>>(out);
}

// round 8
// speedup vs baseline: 3.3483x; 1.5149x over previous
#include <cuda_runtime.h>
#include <cuda_fp16.h>
#include <cstdint>

#define N_ENT    100000
#define N_REL    250000
#define N_TRIG   50000
#define N_ARGS   250000
#define ENT_DIM  288
#define REL_R    256
#define RTYPE_DIM 32
#define ROLE_DIM 256
#define ARG_DIM  576
#define KDIM     1152
#define OUT_DIM  544

#define NKEY     (N_TRIG * 2)       // 100000 (trig, side) segments
#define BLK_KEYS 1024
#define NBLK     ((NKEY + BLK_KEYS - 1) / BLK_KEYS)   // 98
#define NKEY_PAD (NBLK * BLK_KEYS)                    // 100352

// Scratch
__device__ __half g_Sh[(size_t)N_TRIG * KDIM];   // 115.2 MB per-trigger masked sums (fp16)
__device__ __half g_Wh[(size_t)ROLE_DIM * KDIM]; // 0.59 MB: Wcat^T [256,1152] fp16
__device__ int    g_cnt[NKEY_PAD];
__device__ int    g_off[NKEY + 1];
__device__ int    g_cur[NKEY];
__device__ int    g_part[NBLK];
__device__ int    g_ppre[NBLK + 1];
__device__ int4   g_rec[N_ARGS];                 // {rel, ent, rtype, 0} sorted by key

// ---------------------------------------------------------------------------
// helpers
// ---------------------------------------------------------------------------
__device__ __forceinline__ void mma_f16(float* c, const uint32_t* a, const uint32_t* b) {
    asm volatile(
        "mma.sync.aligned.m16n8k16.row.col.f32.f16.f16.f32 "
        "{%0,%1,%2,%3}, {%4,%5,%6,%7}, {%8,%9}, {%0,%1,%2,%3};"
        : "+f"(c[0]), "+f"(c[1]), "+f"(c[2]), "+f"(c[3])
        : "r"(a[0]), "r"(a[1]), "r"(a[2]), "r"(a[3]), "r"(b[0]), "r"(b[1]));
}
__device__ __forceinline__ void cpa16(uint32_t s, const void* g) {
    asm volatile("cp.async.cg.shared.global [%0], [%1], 16;" :: "r"(s), "l"(g));
}
__device__ __forceinline__ uint32_t smem_u32(const void* p) {
    uint32_t a;
    asm("{ .reg .u64 t; cvta.to.shared.u64 t, %1; cvt.u32.u64 %0, t; }"
        : "=r"(a) : "l"(p));
    return a;
}

// ---------------------------------------------------------------------------
// Wh[n][k] = half( k < 576 ? W_in[k][n] : W_out[k-576][n] )
// ---------------------------------------------------------------------------
__global__ void __launch_bounds__(128) transpose_W(
    const float* __restrict__ W_in, const float* __restrict__ W_out)
{
    const int n = blockIdx.x;  // 0..255
    for (int k = threadIdx.x; k < KDIM; k += 128) {
        float w = (k < ARG_DIM) ? __ldg(W_in  + (size_t)k * ROLE_DIM + n)
                                : __ldg(W_out + (size_t)(k - ARG_DIM) * ROLE_DIM + n);
        g_Wh[(size_t)n * KDIM + k] = __float2half_rn(w);
    }
}

// ---------------------------------------------------------------------------
// CSR build: zero -> histogram -> 3-phase parallel scan -> fill
// ---------------------------------------------------------------------------
__global__ void __launch_bounds__(256) zero_cnt() {
    int i = blockIdx.x * 256 + threadIdx.x;
    if (i < NKEY_PAD) g_cnt[i] = 0;
}

__global__ void __launch_bounds__(256) hist_args(
    const int* __restrict__ arg_trig, const int* __restrict__ arg_is_in)
{
    int i = blockIdx.x * 256 + threadIdx.x;
    if (i >= N_ARGS) return;
    atomicAdd(&g_cnt[arg_trig[i] * 2 + arg_is_in[i]], 1);
}

// phase 1: per-block (1024 keys) local exclusive scan + block total
__global__ void __launch_bounds__(256) scan_local()
{
    __shared__ int wsum[8];
    const int tid  = threadIdx.x;
    const int lane = tid & 31;
    const int warp = tid >> 5;
    const int i0   = blockIdx.x * BLK_KEYS + tid * 4;

    int4 v = *reinterpret_cast<const int4*>(g_cnt + i0);
    const int s4 = v.x + v.y + v.z + v.w;
    int inc = s4;
    #pragma unroll
    for (int d = 1; d < 32; d <<= 1) {
        int t = __shfl_up_sync(0xFFFFFFFFu, inc, d);
        if (lane >= d) inc += t;
    }
    if (lane == 31) wsum[warp] = inc;
    __syncthreads();
    int wpre = 0;
    if (warp > 0) {
        #pragma unroll
        for (int j = 0; j < 7; j++) if (j < warp) wpre += wsum[j];
    }
    const int excl = wpre + inc - s4;
    const int o0 = excl, o1 = o0 + v.x, o2 = o1 + v.y, o3 = o2 + v.z;
    if (i0 + 0 < NKEY) g_off[i0 + 0] = o0;
    if (i0 + 1 < NKEY) g_off[i0 + 1] = o1;
    if (i0 + 2 < NKEY) g_off[i0 + 2] = o2;
    if (i0 + 3 < NKEY) g_off[i0 + 3] = o3;
    if (tid == 255) g_part[blockIdx.x] = wpre + inc;
}

// phase 2: one warp scans the 98 block totals
__global__ void __launch_bounds__(32) scan_part()
{
    const int lane = threadIdx.x;
    int v[4];
    int s4 = 0;
    #pragma unroll
    for (int j = 0; j < 4; j++) {
        const int i = lane * 4 + j;
        v[j] = (i < NBLK) ? g_part[i] : 0;
        s4 += v[j];
    }
    int inc = s4;
    #pragma unroll
    for (int d = 1; d < 32; d <<= 1) {
        int t = __shfl_up_sync(0xFFFFFFFFu, inc, d);
        if (lane >= d) inc += t;
    }
    int run = inc - s4;
    #pragma unroll
    for (int j = 0; j < 4; j++) {
        const int i = lane * 4 + j;
        if (i < NBLK) g_ppre[i] = run;
        run += v[j];
    }
    if (lane == 31) g_off[NKEY] = inc;   // grand total
}

// phase 3: add block prefix, init cursors
__global__ void __launch_bounds__(256) scan_add()
{
    const int add = g_ppre[blockIdx.x];
    const int i0  = blockIdx.x * BLK_KEYS + threadIdx.x * 4;
    #pragma unroll
    for (int j = 0; j < 4; j++) {
        const int i = i0 + j;
        if (i < NKEY) {
            const int o = g_off[i] + add;
            g_off[i] = o;
            g_cur[i] = o;
        }
    }
}

__global__ void __launch_bounds__(256) fill_args(
    const int* __restrict__ arg_trig, const int* __restrict__ arg_rel,
    const int* __restrict__ arg_ent, const int* __restrict__ arg_is_in,
    const int* __restrict__ rtype_ids)
{
    int i = blockIdx.x * 256 + threadIdx.x;
    if (i >= N_ARGS) return;
    const int key = arg_trig[i] * 2 + arg_is_in[i];
    const int r   = arg_rel[i];
    const int pos = atomicAdd(&g_cur[key], 1);
    g_rec[pos] = make_int4(r, arg_ent[i], __ldg(rtype_ids + r), 0);
}

// ---------------------------------------------------------------------------
// Aggregate: one warp per (trigger, side). float4 gathers, fp32 register acc,
// single coalesced fp16 write of the 576-elem half-row. No atomics.
// ---------------------------------------------------------------------------
__global__ void __launch_bounds__(256) aggregate(
    const float* __restrict__ ent, const float* __restrict__ rel,
    const float* __restrict__ rtt)
{
    const int w    = (blockIdx.x * 256 + threadIdx.x) >> 5;
    const int lane = threadIdx.x & 31;
    if (w >= NKEY) return;

    const int t    = w >> 1;
    const int isin = w & 1;
    const int off  = __ldg(g_off + w);
    const int end  = __ldg(g_off + w + 1);
    const bool lo8 = lane < 8;

    const float4 z = make_float4(0.f, 0.f, 0.f, 0.f);
    float4 aR0 = z, aR1 = z, aT = z, aE0 = z, aE1 = z, aE2 = z;

    for (int p = off; p < end; p++) {
        const int4 rec = __ldg(g_rec + p);
        const float4* relp = reinterpret_cast<const float4*>(rel + (size_t)rec.x * REL_R);
        const float4* entp = reinterpret_cast<const float4*>(ent + (size_t)rec.y * ENT_DIM);
        const float4* rtp  = reinterpret_cast<const float4*>(rtt + (size_t)rec.z * RTYPE_DIM);

        const float4 r0 = __ldg(relp + lane);
        const float4 r1 = __ldg(relp + lane + 32);
        const float4 e0 = __ldg(entp + lane);
        const float4 e1 = __ldg(entp + lane + 32);
        float4 t0 = z, e2 = z;
        if (lo8) { t0 = __ldg(rtp + lane); e2 = __ldg(entp + lane + 64); }

        aR0.x += r0.x; aR0.y += r0.y; aR0.z += r0.z; aR0.w += r0.w;
        aR1.x += r1.x; aR1.y += r1.y; aR1.z += r1.z; aR1.w += r1.w;
        aT.x  += t0.x; aT.y  += t0.y; aT.z  += t0.z; aT.w  += t0.w;
        aE0.x += e0.x; aE0.y += e0.y; aE0.z += e0.z; aE0.w += e0.w;
        aE1.x += e1.x; aE1.y += e1.y; aE1.z += e1.z; aE1.w += e1.w;
        aE2.x += e2.x; aE2.y += e2.y; aE2.z += e2.z; aE2.w += e2.w;
    }

    __half2* d2 = reinterpret_cast<__half2*>(
        g_Sh + (size_t)t * KDIM + (isin ? 0 : ARG_DIM));
    // rel cols 0..255 -> h2[0..127]
    d2[2 * lane + 0]  = __floats2half2_rn(aR0.x, aR0.y);
    d2[2 * lane + 1]  = __floats2half2_rn(aR0.z, aR0.w);
    d2[64 + 2 * lane + 0] = __floats2half2_rn(aR1.x, aR1.y);
    d2[64 + 2 * lane + 1] = __floats2half2_rn(aR1.z, aR1.w);
    // ent cols 288..575 -> h2[144..287]
    d2[144 + 2 * lane + 0] = __floats2half2_rn(aE0.x, aE0.y);
    d2[144 + 2 * lane + 1] = __floats2half2_rn(aE0.z, aE0.w);
    d2[208 + 2 * lane + 0] = __floats2half2_rn(aE1.x, aE1.y);
    d2[208 + 2 * lane + 1] = __floats2half2_rn(aE1.z, aE1.w);
    if (lo8) {
        // rtype cols 256..287 -> h2[128..143]
        d2[128 + 2 * lane + 0] = __floats2half2_rn(aT.x, aT.y);
        d2[128 + 2 * lane + 1] = __floats2half2_rn(aT.z, aT.w);
        // ent tail cols 544..575 -> h2[272..287]
        d2[272 + 2 * lane + 0] = __floats2half2_rn(aE2.x, aE2.y);
        d2[272 + 2 * lane + 1] = __floats2half2_rn(aE2.z, aE2.w);
    }
}

// ---------------------------------------------------------------------------
// Trigger entity embedding -> out[:, 0:288]
// ---------------------------------------------------------------------------
__global__ void __launch_bounds__(256) copy_trig(
    const float* __restrict__ ent, const int* __restrict__ trig_ent_id,
    float* __restrict__ out)
{
    const int w    = (blockIdx.x * 256 + threadIdx.x) >> 5;
    const int lane = threadIdx.x & 31;
    if (w >= N_TRIG) return;
    const float4* src = reinterpret_cast<const float4*>(
        ent + (size_t)__ldg(trig_ent_id + w) * ENT_DIM);
    float4* dst = reinterpret_cast<float4*>(out + (size_t)w * OUT_DIM);
    dst[lane]      = src[lane];
    dst[lane + 32] = src[lane + 32];
    if (lane < 8) dst[lane + 64] = src[lane + 64];
}

// ---------------------------------------------------------------------------
// fp16 mma.sync GEMM: C[50000,256] = g_Sh[50000,1152] @ g_Wh^T  (f32 accum)
// BM=128, BN=256 (full N), BK=32, 8 warps (4M x 2N), warp tile 32x128.
// mma.m16n8k16: 2 k-steps per chunk.
// ---------------------------------------------------------------------------
#define BM 128
#define BK 32
#define LDH 40                    // halves per row (32 + 8 pad); 80B = 16B mult
#define NKCH (KDIM / BK)          // 36

#define A_BUF_H (BM * LDH)        // 5120 halves = 10240 B
#define B_BUF_H (ROLE_DIM * LDH)  // 10240 halves = 20480 B
#define SM_TOTAL ((2 * A_BUF_H + 2 * B_BUF_H) * 2)  // 61440 B

__global__ void __launch_bounds__(256, 1) gemm_tc(float* __restrict__ out)
{
    extern __shared__ __align__(1024) __half smem[];
    __half* As = smem;
    __half* Bs = smem + 2 * A_BUF_H;
    const uint32_t sbA = smem_u32(As);
    const uint32_t sbB = smem_u32(Bs);

    const int tid  = threadIdx.x;
    const int wid  = tid >> 5;
    const int lane = tid & 31;
    const int wm   = wid & 3;
    const int wn   = wid >> 2;
    const int qr   = lane >> 2;
    const int qc   = lane & 3;
    const int m0   = blockIdx.x * BM;

    float acc[2][16][4];
    #pragma unroll
    for (int mi = 0; mi < 2; mi++)
        #pragma unroll
        for (int ni = 0; ni < 16; ni++)
            #pragma unroll
            for (int q = 0; q < 4; q++) acc[mi][ni][q] = 0.f;

    auto load_chunk = [&](int c, int buf) {
        const int k0 = c * BK;
        const uint32_t aB = sbA + buf * (A_BUF_H * 2);
        const uint32_t bB = sbB + buf * (B_BUF_H * 2);
        // A: 128 rows x 4 segs of 8 halves (16B)
        #pragma unroll
        for (int j = 0; j < 2; j++) {
            const int idx = tid + j * 256;
            const int row = idx >> 2, seg = idx & 3;
            int m = m0 + row; if (m > N_TRIG - 1) m = N_TRIG - 1;
            cpa16(aB + (uint32_t)(row * (LDH * 2) + seg * 16),
                  g_Sh + (size_t)m * KDIM + k0 + seg * 8);
        }
        // B: 256 rows x 4 segs
        #pragma unroll
        for (int j = 0; j < 4; j++) {
            const int idx = tid + j * 256;
            const int row = idx >> 2, seg = idx & 3;
            cpa16(bB + (uint32_t)(row * (LDH * 2) + seg * 16),
                  g_Wh + (size_t)row * KDIM + k0 + seg * 8);
        }
        asm volatile("cp.async.commit_group;" ::: "memory");
    };

    load_chunk(0, 0);
    load_chunk(1, 1);

    for (int c = 0; c < NKCH; c++) {
        const int buf = c & 1;
        if (c + 2 < NKCH) asm volatile("cp.async.wait_group 1;" ::: "memory");
        else              asm volatile("cp.async.wait_group 0;" ::: "memory");
        __syncthreads();

        const __half* A = As + buf * A_BUF_H;
        const __half* B = Bs + buf * B_BUF_H;

        #pragma unroll
        for (int ks = 0; ks < 2; ks++) {
            const int kk = ks * 16;
            uint32_t a[2][4];
            #pragma unroll
            for (int mi = 0; mi < 2; mi++) {
                const int r = wm * 32 + mi * 16 + qr;
                a[mi][0] = *reinterpret_cast<const uint32_t*>(&A[r * LDH + kk + 2 * qc]);
                a[mi][1] = *reinterpret_cast<const uint32_t*>(&A[(r + 8) * LDH + kk + 2 * qc]);
                a[mi][2] = *reinterpret_cast<const uint32_t*>(&A[r * LDH + kk + 8 + 2 * qc]);
                a[mi][3] = *reinterpret_cast<const uint32_t*>(&A[(r + 8) * LDH + kk + 8 + 2 * qc]);
            }
            #pragma unroll
            for (int h = 0; h < 2; h++) {
                uint32_t b[8][2];
                #pragma unroll
                for (int nj = 0; nj < 8; nj++) {
                    const int cb = wn * 128 + (h * 8 + nj) * 8 + qr;
                    b[nj][0] = *reinterpret_cast<const uint32_t*>(&B[cb * LDH + kk + 2 * qc]);
                    b[nj][1] = *reinterpret_cast<const uint32_t*>(&B[cb * LDH + kk + 8 + 2 * qc]);
                }
                #pragma unroll
                for (int mi = 0; mi < 2; mi++)
                    #pragma unroll
                    for (int nj = 0; nj < 8; nj++)
                        mma_f16(acc[mi][h * 8 + nj], a[mi], b[nj]);
            }
        }
        __syncthreads();
        if (c + 2 < NKCH) load_chunk(c + 2, buf);
    }

    #pragma unroll
    for (int mi = 0; mi < 2; mi++) {
        const int m_lo = m0 + wm * 32 + mi * 16 + qr;
        #pragma unroll
        for (int ni = 0; ni < 16; ni++) {
            const int n = ENT_DIM + wn * 128 + ni * 8 + qc * 2;
            if (m_lo < N_TRIG)
                *reinterpret_cast<float2*>(out + (size_t)m_lo * OUT_DIM + n) =
                    make_float2(acc[mi][ni][0], acc[mi][ni][1]);
            if (m_lo + 8 < N_TRIG)
                *reinterpret_cast<float2*>(out + (size_t)(m_lo + 8) * OUT_DIM + n) =
                    make_float2(acc[mi][ni][2], acc[mi][ni][3]);
        }
    }
}

// ---------------------------------------------------------------------------
extern "C" void kernel_launch(void* const* d_in, const int* in_sizes, int n_in,
                              void* d_out, int out_size)
{
    const float* ent       = (const float*)d_in[0];
    const float* rel       = (const float*)d_in[1];
    const float* rtt       = (const float*)d_in[2];
    const float* W_in      = (const float*)d_in[3];
    const float* W_out     = (const float*)d_in[4];
    const int*   rtype_ids = (const int*)d_in[5];
    const int*   trig_ent  = (const int*)d_in[6];
    const int*   arg_trig  = (const int*)d_in[7];
    const int*   arg_rel   = (const int*)d_in[8];
    const int*   arg_ent   = (const int*)d_in[9];
    const int*   arg_is_in = (const int*)d_in[10];
    float* out = (float*)d_out;

    (void)in_sizes; (void)n_in; (void)out_size;

    transpose_W<<<ROLE_DIM, 128>>>(W_in, W_out);
    zero_cnt<<<(NKEY_PAD + 255) / 256, 256>>>();
    hist_args<<<(N_ARGS + 255) / 256, 256>>>(arg_trig, arg_is_in);
    scan_local<<<NBLK, 256>>>();
    scan_part<<<1, 32>>>();
    scan_add<<<NBLK, 256>>>();
    fill_args<<<(N_ARGS + 255) / 256, 256>>>(
        arg_trig, arg_rel, arg_ent, arg_is_in, rtype_ids);
    aggregate<<<(NKEY * 32 + 255) / 256, 256>>>(ent, rel, rtt);
    copy_trig<<<(N_TRIG * 32 + 255) / 256, 256>>>(ent, trig_ent, out);

    cudaFuncSetAttribute(gemm_tc, cudaFuncAttributeMaxDynamicSharedMemorySize, SM_TOTAL);
    gemm_tc<<<(N_TRIG + BM - 1) / BM, 256, SM_TOTAL>>>(out);
}